// round 8
// baseline (speedup 1.0000x reference)
#include <cuda_runtime.h>
#include <cuda_fp16.h>
#include <math.h>
#include <stdint.h>

// Problem constants
#define BB 2
#define SS 2048
#define DD 1024
#define FF 4096
#define HH 16
#define DKK 64
#define MM (BB*SS)          // 4096

#define WQ0 0
#define WK0 (DD*DD)
#define WV0 (2*DD*DD)
#define WO0 (3*DD*DD)
#define W10 (4*DD*DD)
#define W20 (8*DD*DD)
#define WTOT (12*DD*DD)

// ---------------- scratch (static device memory; no allocation APIs) ----------------
__device__ __align__(256) float  g_q  [MM*DD];     // fp32 Q for flash (split in-kernel)
__device__ __align__(256) __half g_khh[MM*DD];
__device__ __align__(256) __half g_khl[MM*DD];
__device__ __align__(256) __half g_vh [MM*DD];
__device__ __align__(256) __half g_ath[MM*DD];     // attention output (fp16)
__device__ __align__(256) float  g_x1 [MM*DD];
__device__ __align__(256) __half g_xnh[MM*DD];
__device__ __align__(256) __half g_xnl[MM*DD];
__device__ __align__(256) __half g_hh [MM*FF];
__device__ __align__(256) __half g_wh [WTOT];
__device__ __align__(256) __half g_wl [WTOT];

// ---------------- helpers ----------------
__device__ __forceinline__ float warpSum(float v) {
#pragma unroll
    for (int o = 16; o > 0; o >>= 1) v += __shfl_xor_sync(0xffffffffu, v, o);
    return v;
}
__device__ float blockSum(float v) {
    __shared__ float sh[8];
    int lane = threadIdx.x & 31, w = threadIdx.x >> 5;
    v = warpSum(v);
    if (lane == 0) sh[w] = v;
    __syncthreads();
    if (w == 0) {
        float t = (lane < 8) ? sh[lane] : 0.0f;
        t = warpSum(t);
        if (lane == 0) sh[0] = t;
    }
    __syncthreads();
    float out = sh[0];
    __syncthreads();
    return out;
}
__device__ __forceinline__ void hsplit(float f, __half& h, __half& l) {
    h = __float2half_rn(f);
    l = __float2half_rn(f - __half2float(h));
}

// ---------------- fp32 -> (hi,lo) fp16 split kernel (weights) ----------------
__global__ void conv_kernel(const float* __restrict__ s,
                            __half* __restrict__ ho, __half* __restrict__ lo, int n4) {
    int i = blockIdx.x * 256 + threadIdx.x;
    if (i >= n4) return;
    float4 v = ((const float4*)s)[i];
    __half h0, h1, h2, h3, l0, l1, l2, l3;
    hsplit(v.x, h0, l0); hsplit(v.y, h1, l1);
    hsplit(v.z, h2, l2); hsplit(v.w, h3, l3);
    __half2 p;
    p.x = h0; p.y = h1; ((__half2*)ho)[2 * i] = p;
    p.x = h2; p.y = h3; ((__half2*)ho)[2 * i + 1] = p;
    p.x = l0; p.y = l1; ((__half2*)lo)[2 * i] = p;
    p.x = l2; p.y = l3; ((__half2*)lo)[2 * i + 1] = p;
}

// ---------------- LayerNorm -> hi/lo fp16 ----------------
__global__ void ln_kernel(const float* __restrict__ x,
                          __half* __restrict__ yh, __half* __restrict__ yl,
                          const float* __restrict__ alpha, const float* __restrict__ beta) {
    long long row = blockIdx.x;
    const float* xr = x + row * DD;
    float v[4];
    float s = 0.0f;
#pragma unroll
    for (int r = 0; r < 4; r++) {
        v[r] = xr[threadIdx.x + r * 256];
        s += v[r];
    }
    float mean = blockSum(s) * (1.0f / DD);
    float s2 = 0.0f;
#pragma unroll
    for (int r = 0; r < 4; r++) {
        float d = v[r] - mean;
        s2 += d * d;
    }
    float var = blockSum(s2) * (1.0f / (DD - 1));
    float a = alpha[0], b = beta[0];
    float inv = a / (sqrtf(var) + 1e-6f);
#pragma unroll
    for (int r = 0; r < 4; r++) {
        int idx = threadIdx.x + r * 256;
        float o = (v[r] - mean) * inv + b;
        __half h, l;
        hsplit(o, h, l);
        yh[row * DD + idx] = h;
        yl[row * DD + idx] = l;
    }
}

// ---------------- PTX primitives ----------------
__device__ __forceinline__ void mma_f16(float* c, const uint32_t* a,
                                        uint32_t b0, uint32_t b1) {
    asm volatile(
        "mma.sync.aligned.m16n8k16.row.col.f32.f16.f16.f32 "
        "{%0,%1,%2,%3},{%4,%5,%6,%7},{%8,%9},{%0,%1,%2,%3};"
        : "+f"(c[0]), "+f"(c[1]), "+f"(c[2]), "+f"(c[3])
        : "r"(a[0]), "r"(a[1]), "r"(a[2]), "r"(a[3]), "r"(b0), "r"(b1));
}
__device__ __forceinline__ void ldmx4(uint32_t addr, uint32_t& r0, uint32_t& r1,
                                      uint32_t& r2, uint32_t& r3) {
    asm volatile("ldmatrix.sync.aligned.m8n8.x4.shared.b16 {%0,%1,%2,%3}, [%4];"
                 : "=r"(r0), "=r"(r1), "=r"(r2), "=r"(r3) : "r"(addr));
}
__device__ __forceinline__ void ldmx2t(uint32_t addr, uint32_t& r0, uint32_t& r1) {
    asm volatile("ldmatrix.sync.aligned.m8n8.x2.trans.shared.b16 {%0,%1}, [%2];"
                 : "=r"(r0), "=r"(r1) : "r"(addr));
}
__device__ __forceinline__ void cp16(uint32_t d, const void* s) {
    asm volatile("cp.async.cg.shared.global [%0], [%1], 16;" :: "r"(d), "l"(s));
}
__device__ __forceinline__ void cpcommit() { asm volatile("cp.async.commit_group;"); }
template<int N> __device__ __forceinline__ void cpwait() {
    asm volatile("cp.async.wait_group %0;" :: "n"(N));
}
__device__ __forceinline__ uint32_t s2u(const void* p) {
    uint32_t a;
    asm("{ .reg .u64 t; cvta.to.shared.u64 t, %1; cvt.u32.u64 %0, t; }" : "=r"(a) : "l"(p));
    return a;
}
__device__ __forceinline__ uint32_t packh2(float a, float b) {
    __half2 h = __floats2half2_rn(a, b);
    return *(uint32_t*)&h;
}

// ---------------- fp16 NT GEMM ----------------
// C[m,n] = sum_k A[m,k]*B[n,k]. BM=BN=128, BK=32, cp.async pipeline, ldmatrix.
// SPLIT=1: 3-mma hi/lo split, 2-stage (80KB). SPLIT=0: plain 1-mma, 3-stage (61KB).
// outMode: 0 = fp32 C (+res opt), 1 = half Ch (hi only, relu opt), 2 = half Ch+Cl.
#define BKD 32
#define STRD 40                          // halves; 80B row stride, ldmatrix conflict-free
#define TILE_E (128*STRD)

template<int SPLIT>
__global__ void __launch_bounds__(256, 2)
gemm_h(const __half* __restrict__ Ah, const __half* __restrict__ Al,
       const __half* __restrict__ Bh, const __half* __restrict__ Bl,
       const float* __restrict__ bias, const float* __restrict__ res,
       float* __restrict__ C, __half* __restrict__ Ch, __half* __restrict__ Cl,
       int M, int N, int K, int doRelu, int doRes, int outMode)
{
    constexpr int NARR = SPLIT ? 4 : 2;
    constexpr int STG  = SPLIT ? 2 : 3;
    extern __shared__ __half sm[];
    const uint32_t sbase = s2u(sm);

    const int m0 = blockIdx.y * 128, n0 = blockIdx.x * 128;
    const int t = threadIdx.x, lane = t & 31, w = t >> 5;
    const int gid = lane >> 2, tig = lane & 3;
    const int wm = w >> 2, wn = w & 3;
    const int mBase = wm * 64, nBase = wn * 32;
    const int lr = lane & 7, lj = lane >> 3;

    float acc[4][4][4];
#pragma unroll
    for (int i = 0; i < 4; i++)
#pragma unroll
        for (int j = 0; j < 4; j++)
#pragma unroll
            for (int r = 0; r < 4; r++) acc[i][j][r] = 0.0f;

    const __half* gsrc[NARR];
    if (SPLIT) { gsrc[0] = Ah; gsrc[1] = Al; gsrc[2] = Bh; gsrc[3] = Bl; }
    else       { gsrc[0] = Ah; gsrc[1] = Bh; }

    auto issue = [&](int kt, int s) {
        int k0 = kt * BKD;
#pragma unroll
        for (int arr = 0; arr < NARR; arr++) {
            const int rb = (arr < (SPLIT ? 2 : 1)) ? m0 : n0;
            const __half* src = gsrc[arr];
            uint32_t dst = sbase + (uint32_t)(s * NARR + arr) * (TILE_E * 2);
#pragma unroll
            for (int i = 0; i < 2; i++) {
                int c = t + i * 256;
                int row = c >> 2, col = (c & 3) * 8;
                cp16(dst + (uint32_t)(row * STRD + col) * 2,
                     src + (long long)(rb + row) * K + k0 + col);
            }
        }
    };

    const int KT = K / BKD;
    issue(0, 0); cpcommit();
    if (STG == 3) { issue(1, 1); cpcommit(); }

    for (int kt = 0; kt < KT; kt++) {
        if (STG == 3 && kt + 1 < KT) cpwait<1>(); else cpwait<0>();
        __syncthreads();
        if (kt + STG - 1 < KT) { issue(kt + STG - 1, (kt + STG - 1) % STG); cpcommit(); }

        const int buf = kt % STG;
        const uint32_t uAh = sbase + (uint32_t)(buf * NARR + 0) * (TILE_E * 2);
        const uint32_t uAl = SPLIT ? sbase + (uint32_t)(buf * NARR + 1) * (TILE_E * 2) : 0;
        const uint32_t uBh = sbase + (uint32_t)(buf * NARR + (SPLIT ? 2 : 1)) * (TILE_E * 2);
        const uint32_t uBl = SPLIT ? sbase + (uint32_t)(buf * NARR + 3) * (TILE_E * 2) : 0;

#pragma unroll
        for (int kk = 0; kk < BKD; kk += 16) {
            uint32_t bh[4][2], bl[4][2];
#pragma unroll
            for (int p = 0; p < 2; p++) {
                uint32_t off = (uint32_t)((nBase + p * 16 + lr + (lj >> 1) * 8) * STRD
                                          + kk + (lj & 1) * 8) * 2;
                ldmx4(uBh + off, bh[2 * p][0], bh[2 * p][1], bh[2 * p + 1][0], bh[2 * p + 1][1]);
                if (SPLIT)
                    ldmx4(uBl + off, bl[2 * p][0], bl[2 * p][1], bl[2 * p + 1][0], bl[2 * p + 1][1]);
            }
#pragma unroll
            for (int mt = 0; mt < 4; mt++) {
                uint32_t ah[4], al4[4];
                uint32_t aoff = (uint32_t)((mBase + mt * 16 + lr + (lj & 1) * 8) * STRD
                                           + kk + (lj >> 1) * 8) * 2;
                ldmx4(uAh + aoff, ah[0], ah[1], ah[2], ah[3]);
                if (SPLIT) ldmx4(uAl + aoff, al4[0], al4[1], al4[2], al4[3]);
#pragma unroll
                for (int nt = 0; nt < 4; nt++) {
                    mma_f16(acc[mt][nt], ah, bh[nt][0], bh[nt][1]);
                    if (SPLIT) {
                        mma_f16(acc[mt][nt], ah, bl[nt][0], bl[nt][1]);
                        mma_f16(acc[mt][nt], al4, bh[nt][0], bh[nt][1]);
                    }
                }
            }
        }
    }

    // ---- epilogue
#pragma unroll
    for (int mt = 0; mt < 4; mt++) {
#pragma unroll
        for (int nt = 0; nt < 4; nt++) {
            int row = m0 + mBase + mt * 16 + gid;
            int col = n0 + nBase + nt * 8 + tig * 2;
            float b0 = bias[col], b1 = bias[col + 1];
#pragma unroll
            for (int half = 0; half < 2; half++) {
                int r = row + half * 8;
                float v0 = acc[mt][nt][half * 2 + 0] + b0;
                float v1 = acc[mt][nt][half * 2 + 1] + b1;
                if (doRelu) { v0 = fmaxf(v0, 0.f); v1 = fmaxf(v1, 0.f); }
                if (outMode == 0) {
                    if (doRes) {
                        float2 rr = *(const float2*)(res + (long long)r * N + col);
                        v0 += rr.x; v1 += rr.y;
                    }
                    *(float2*)(C + (long long)r * N + col) = make_float2(v0, v1);
                } else if (outMode == 1) {
                    __half2 p = __floats2half2_rn(v0, v1);
                    *(__half2*)(Ch + (long long)r * N + col) = p;
                } else {
                    __half h0, l0, h1, l1;
                    hsplit(v0, h0, l0); hsplit(v1, h1, l1);
                    __half2 p;
                    p.x = h0; p.y = h1;
                    *(__half2*)(Ch + (long long)r * N + col) = p;
                    p.x = l0; p.y = l1;
                    *(__half2*)(Cl + (long long)r * N + col) = p;
                }
            }
        }
    }
}

#define GEMM_SMEM_S1 (2 * 4 * TILE_E * 2)   // 81920
#define GEMM_SMEM_S0 (3 * 2 * TILE_E * 2)   // 61440

// ---------------- flash attention, fp16, 3-stage K/V pipeline ----------------
// Grid (S/128, B*H), 256 thr = 8 warps; warp w owns q-rows [w*16, (w+1)*16).
// K pre-split (khh/khl fp16), V pre-converted (vh). Q fp32, split in-kernel.
// QK^T: 3-mma split-fp16. PV: plain fp16, A-frags straight from softmax registers.
// One __syncthreads per key-block (mask double-buffered).
#define KST 72                      // halves per smem row (144B)
#define FL_BUF (128*KST)            // halves per array per stage
#define QSTR 68
#define NKB (SS/128)                // 16
#define FLASH_SMEM (9 * FL_BUF * 2) // 3 stages x 3 arrays

__global__ void __launch_bounds__(256, 1)
flash_kernel(const float* __restrict__ Q, const __half* __restrict__ Khh,
             const __half* __restrict__ Khl, const __half* __restrict__ Vh,
             const int* __restrict__ mask, __half* __restrict__ O)
{
    extern __shared__ __half fsm[];
    __shared__ int Ms[2][128];
    const uint32_t sb = s2u(fsm);

    const int bh = blockIdx.y;
    const int b = bh >> 4, h = bh & 15;
    const int q0 = blockIdx.x * 128;
    const int t = threadIdx.x, lane = t & 31, w = t >> 5;
    const int gid = lane >> 2, tig = lane & 3;

    auto issue = [&](int kb, int buf) {
        const long long rowbase = (long long)b * SS + kb * 128;
        const __half* srcs[3] = { Khh, Khl, Vh };
#pragma unroll
        for (int arr = 0; arr < 3; arr++) {
            const __half* src = srcs[arr];
            uint32_t dst = sb + (uint32_t)(buf * 3 + arr) * (FL_BUF * 2);
#pragma unroll
            for (int i = 0; i < 4; i++) {
                int idx = t + i * 256;
                int row = idx >> 3, pc = idx & 7;
                cp16(dst + (uint32_t)(row * KST + pc * 8) * 2,
                     src + (rowbase + row) * DD + h * DKK + pc * 8);
            }
        }
    };

    // prologue: key-blocks 0 and 1 in flight; stage+split Q in buffer-2 overlay
    issue(0, 0); cpcommit();
    issue(1, 1); cpcommit();

    float* Qs = (float*)(fsm + 6 * FL_BUF);     // overlay on buffer 2 (untouched yet)
    {
        const float* Qbase = Q + ((long long)(b * SS + q0)) * DD + h * DKK;
        for (int i = t; i < 2048; i += 256) {
            int r = i >> 4, c = (i & 15) * 4;
            *(float4*)&Qs[r * QSTR + c] = *(const float4*)(Qbase + (long long)r * DD + c);
        }
    }
    __syncthreads();

    uint32_t qh[4][4], ql[4][4];
    {
        int r0 = w * 16 + gid;
#pragma unroll
        for (int ks = 0; ks < 4; ks++) {
            int k0 = ks * 16;
            float f00 = Qs[r0 * QSTR + k0 + 2 * tig],       f01 = Qs[r0 * QSTR + k0 + 2 * tig + 1];
            float f10 = Qs[(r0 + 8) * QSTR + k0 + 2 * tig], f11 = Qs[(r0 + 8) * QSTR + k0 + 2 * tig + 1];
            float f20 = Qs[r0 * QSTR + k0 + 8 + 2 * tig],       f21 = Qs[r0 * QSTR + k0 + 8 + 2 * tig + 1];
            float f30 = Qs[(r0 + 8) * QSTR + k0 + 8 + 2 * tig], f31 = Qs[(r0 + 8) * QSTR + k0 + 8 + 2 * tig + 1];
            __half h0, l0, h1, l1;
            hsplit(f00, h0, l0); hsplit(f01, h1, l1);
            qh[ks][0] = packh2(__half2float(h0), __half2float(h1));
            ql[ks][0] = packh2(__half2float(l0), __half2float(l1));
            hsplit(f10, h0, l0); hsplit(f11, h1, l1);
            qh[ks][1] = packh2(__half2float(h0), __half2float(h1));
            ql[ks][1] = packh2(__half2float(l0), __half2float(l1));
            hsplit(f20, h0, l0); hsplit(f21, h1, l1);
            qh[ks][2] = packh2(__half2float(h0), __half2float(h1));
            ql[ks][2] = packh2(__half2float(l0), __half2float(l1));
            hsplit(f30, h0, l0); hsplit(f31, h1, l1);
            qh[ks][3] = packh2(__half2float(h0), __half2float(h1));
            ql[ks][3] = packh2(__half2float(l0), __half2float(l1));
        }
    }

    float acc[8][4];
#pragma unroll
    for (int i = 0; i < 8; i++)
#pragma unroll
        for (int r = 0; r < 4; r++) acc[i][r] = 0.0f;
    float mrow0 = -1e30f, mrow1 = -1e30f;
    float lrow0 = 0.0f, lrow1 = 0.0f;

    for (int kb = 0; kb < NKB; kb++) {
        if (kb + 1 < NKB) cpwait<1>(); else cpwait<0>();
        if (t < 128) Ms[kb & 1][t] = mask[(long long)b * SS + kb * 128 + t];
        __syncthreads();            // buffer kb%3 ready; Q-frag reads done (kb==0)
        if (kb + 2 < NKB) { issue(kb + 2, (kb + 2) % 3); cpcommit(); }

        const int buf = kb % 3;
        const uint32_t bKhh = sb + (uint32_t)(buf * 3 + 0) * (FL_BUF * 2);
        const uint32_t bKhl = sb + (uint32_t)(buf * 3 + 1) * (FL_BUF * 2);
        const uint32_t bV   = sb + (uint32_t)(buf * 3 + 2) * (FL_BUF * 2);
        const int lr = lane & 7, lj = lane >> 3;
        const int* Mrow = Ms[kb & 1];

        // ---- QK^T: 16 key-tiles of 8, 4 k16 steps, 3-term split
        float s[16][4];
#pragma unroll
        for (int nt = 0; nt < 16; nt++) {
            s[nt][0] = 0.f; s[nt][1] = 0.f; s[nt][2] = 0.f; s[nt][3] = 0.f;
        }
#pragma unroll
        for (int ks = 0; ks < 4; ks++) {
#pragma unroll
            for (int pp = 0; pp < 8; pp++) {
                uint32_t off = (uint32_t)((pp * 16 + lr + (lj >> 1) * 8) * KST
                                          + ks * 16 + (lj & 1) * 8) * 2;
                uint32_t r0, r1, r2, r3, e0, e1, e2, e3;
                ldmx4(bKhh + off, r0, r1, r2, r3);
                ldmx4(bKhl + off, e0, e1, e2, e3);
                mma_f16(s[2 * pp],     qh[ks], r0, r1);
                mma_f16(s[2 * pp],     ql[ks], r0, r1);
                mma_f16(s[2 * pp],     qh[ks], e0, e1);
                mma_f16(s[2 * pp + 1], qh[ks], r2, r3);
                mma_f16(s[2 * pp + 1], ql[ks], r2, r3);
                mma_f16(s[2 * pp + 1], qh[ks], e2, e3);
            }
        }

        // ---- mask
#pragma unroll
        for (int nt = 0; nt < 16; nt++) {
            int c = nt * 8 + 2 * tig;
            if (Mrow[c] == 0)     { s[nt][0] = -1e30f; s[nt][2] = -1e30f; }
            if (Mrow[c + 1] == 0) { s[nt][1] = -1e30f; s[nt][3] = -1e30f; }
        }

        // ---- online softmax (rows gid, gid+8)
        float tm0 = -1e30f, tm1 = -1e30f;
#pragma unroll
        for (int nt = 0; nt < 16; nt++) {
            tm0 = fmaxf(tm0, fmaxf(s[nt][0], s[nt][1]));
            tm1 = fmaxf(tm1, fmaxf(s[nt][2], s[nt][3]));
        }
        tm0 = fmaxf(tm0, __shfl_xor_sync(0xffffffffu, tm0, 1));
        tm0 = fmaxf(tm0, __shfl_xor_sync(0xffffffffu, tm0, 2));
        tm1 = fmaxf(tm1, __shfl_xor_sync(0xffffffffu, tm1, 1));
        tm1 = fmaxf(tm1, __shfl_xor_sync(0xffffffffu, tm1, 2));
        float mn0 = fmaxf(mrow0, tm0), mn1 = fmaxf(mrow1, tm1);
        float sc0 = __expf(mrow0 - mn0), sc1 = __expf(mrow1 - mn1);
        mrow0 = mn0; mrow1 = mn1;
        float rs0 = 0.f, rs1 = 0.f;
#pragma unroll
        for (int nt = 0; nt < 16; nt++) {
            s[nt][0] = __expf(s[nt][0] - mn0);
            s[nt][1] = __expf(s[nt][1] - mn0);
            s[nt][2] = __expf(s[nt][2] - mn1);
            s[nt][3] = __expf(s[nt][3] - mn1);
            rs0 += s[nt][0] + s[nt][1];
            rs1 += s[nt][2] + s[nt][3];
        }
        rs0 += __shfl_xor_sync(0xffffffffu, rs0, 1);
        rs0 += __shfl_xor_sync(0xffffffffu, rs0, 2);
        rs1 += __shfl_xor_sync(0xffffffffu, rs1, 1);
        rs1 += __shfl_xor_sync(0xffffffffu, rs1, 2);
        lrow0 = lrow0 * sc0 + rs0;
        lrow1 = lrow1 * sc1 + rs1;
#pragma unroll
        for (int nt = 0; nt < 8; nt++) {
            acc[nt][0] *= sc0; acc[nt][1] *= sc0;
            acc[nt][2] *= sc1; acc[nt][3] *= sc1;
        }

        // ---- P @ V: A-frags straight from registers, V via ldmatrix.trans
        const int li = lane & 15;
#pragma unroll
        for (int ks = 0; ks < 8; ks++) {
            uint32_t a[4];
            a[0] = packh2(s[2 * ks][0],     s[2 * ks][1]);
            a[1] = packh2(s[2 * ks][2],     s[2 * ks][3]);
            a[2] = packh2(s[2 * ks + 1][0], s[2 * ks + 1][1]);
            a[3] = packh2(s[2 * ks + 1][2], s[2 * ks + 1][3]);
#pragma unroll
            for (int nt2 = 0; nt2 < 8; nt2++) {
                uint32_t off = (uint32_t)((ks * 16 + (li & 7) + (li >> 3) * 8) * KST
                                          + nt2 * 8) * 2;
                uint32_t b0, b1;
                ldmx2t(bV + off, b0, b1);
                mma_f16(acc[nt2], a, b0, b1);
            }
        }
    }

    // ---- epilogue: normalize, write fp16 attn
    float inv0 = 1.0f / lrow0, inv1 = 1.0f / lrow1;
    long long rowg = (long long)(b * SS + q0 + w * 16 + gid);
#pragma unroll
    for (int nt = 0; nt < 8; nt++) {
        int col = h * DKK + nt * 8 + 2 * tig;
        __half2 p0 = __floats2half2_rn(acc[nt][0] * inv0, acc[nt][1] * inv0);
        __half2 p1 = __floats2half2_rn(acc[nt][2] * inv1, acc[nt][3] * inv1);
        *(__half2*)(O + rowg * DD + col) = p0;
        *(__half2*)(O + (rowg + 8) * DD + col) = p1;
    }
}

// ---------------- host launch ----------------
extern "C" void kernel_launch(void* const* d_in, const int* in_sizes, int n_in,
                              void* d_out, int out_size) {
    const float* x      = (const float*)d_in[0];
    const int*   mask   = (const int*)  d_in[1];
    const float* wq     = (const float*)d_in[2];
    const float* bq     = (const float*)d_in[3];
    const float* wk     = (const float*)d_in[4];
    const float* bk     = (const float*)d_in[5];
    const float* wv     = (const float*)d_in[6];
    const float* bv     = (const float*)d_in[7];
    const float* wo     = (const float*)d_in[8];
    const float* bo     = (const float*)d_in[9];
    const float* w1     = (const float*)d_in[10];
    const float* b1     = (const float*)d_in[11];
    const float* w2     = (const float*)d_in[12];
    const float* b2     = (const float*)d_in[13];
    const float* alpha1 = (const float*)d_in[14];
    const float* beta1  = (const float*)d_in[15];
    const float* alpha2 = (const float*)d_in[16];
    const float* beta2  = (const float*)d_in[17];
    float* out = (float*)d_out;

    float *q, *x1;
    __half *khh, *khl, *vh, *ath, *xnh, *xnl, *hh, *wh, *wl;
    cudaGetSymbolAddress((void**)&q,   g_q);
    cudaGetSymbolAddress((void**)&x1,  g_x1);
    cudaGetSymbolAddress((void**)&khh, g_khh);
    cudaGetSymbolAddress((void**)&khl, g_khl);
    cudaGetSymbolAddress((void**)&vh,  g_vh);
    cudaGetSymbolAddress((void**)&ath, g_ath);
    cudaGetSymbolAddress((void**)&xnh, g_xnh);
    cudaGetSymbolAddress((void**)&xnl, g_xnl);
    cudaGetSymbolAddress((void**)&hh,  g_hh);
    cudaGetSymbolAddress((void**)&wh,  g_wh);
    cudaGetSymbolAddress((void**)&wl,  g_wl);

    cudaFuncSetAttribute(flash_kernel, cudaFuncAttributeMaxDynamicSharedMemorySize, FLASH_SMEM);
    cudaFuncSetAttribute(gemm_h<1>, cudaFuncAttributeMaxDynamicSharedMemorySize, GEMM_SMEM_S1);
    cudaFuncSetAttribute(gemm_h<0>, cudaFuncAttributeMaxDynamicSharedMemorySize, GEMM_SMEM_S0);

    const int n4w = DD * DD / 4;

    // launches 1-4: split attention weights (ncu -s 5 -c 1 captures launch #6)
    conv_kernel<<<n4w / 256, 256>>>(wq, wh + WQ0, wl + WQ0, n4w);
    conv_kernel<<<n4w / 256, 256>>>(wk, wh + WK0, wl + WK0, n4w);
    conv_kernel<<<n4w / 256, 256>>>(wv, wh + WV0, wl + WV0, n4w);
    conv_kernel<<<n4w / 256, 256>>>(wo, wh + WO0, wl + WO0, n4w);

    // launch 5: LN1 -> xn hi/lo
    ln_kernel<<<MM, 256>>>(x, xnh, xnl, alpha1, beta1);

    // launches 6-8: projections (launch #6 = split q-GEMM -> profiled)
    {
        dim3 g(DD / 128, MM / 128);
        gemm_h<1><<<g, 256, GEMM_SMEM_S1>>>(xnh, xnl, wh + WQ0, wl + WQ0, bq, nullptr,
                                            q, nullptr, nullptr, MM, DD, DD, 0, 0, 0);
        gemm_h<1><<<g, 256, GEMM_SMEM_S1>>>(xnh, xnl, wh + WK0, wl + WK0, bk, nullptr,
                                            nullptr, khh, khl, MM, DD, DD, 0, 0, 2);
        gemm_h<0><<<g, 256, GEMM_SMEM_S0>>>(xnh, nullptr, wh + WV0, nullptr, bv, nullptr,
                                            nullptr, vh, nullptr, MM, DD, DD, 0, 0, 1);
    }

    // fused attention (fp16) -> ath
    {
        dim3 g(SS / 128, BB * HH);
        flash_kernel<<<g, 256, FLASH_SMEM>>>(q, khh, khl, vh, mask, ath);
    }

    // x1 = x + attn @ wo^T + bo  (plain fp16)
    {
        dim3 g(DD / 128, MM / 128);
        gemm_h<0><<<g, 256, GEMM_SMEM_S0>>>(ath, nullptr, wh + WO0, nullptr, bo, x,
                                            x1, nullptr, nullptr, MM, DD, DD, 0, 1, 0);
    }

    // split FFN weights (just-in-time, keeps launch #6 = q-GEMM)
    conv_kernel<<<4 * n4w / 256, 256>>>(w1, wh + W10, wl + W10, 4 * n4w);
    conv_kernel<<<4 * n4w / 256, 256>>>(w2, wh + W20, wl + W20, 4 * n4w);

    // LN2 -> xn hi/lo
    ln_kernel<<<MM, 256>>>(x1, xnh, xnl, alpha2, beta2);

    // h = relu(xn @ w1^T + b1) -> fp16 (plain)
    {
        dim3 g(FF / 128, MM / 128);
        gemm_h<0><<<g, 256, GEMM_SMEM_S0>>>(xnh, nullptr, wh + W10, nullptr, b1, nullptr,
                                            nullptr, hh, nullptr, MM, FF, DD, 1, 0, 1);
    }

    // out = x1 + h @ w2^T + b2  (plain fp16)
    {
        dim3 g(DD / 128, MM / 128);
        gemm_h<0><<<g, 256, GEMM_SMEM_S0>>>(hh, nullptr, wh + W20, nullptr, b2, x1,
                                            out, nullptr, nullptr, MM, DD, FF, 0, 1, 0);
    }
}

// round 9
// speedup vs baseline: 1.0587x; 1.0587x over previous
#include <cuda_runtime.h>
#include <cuda_fp16.h>
#include <math.h>
#include <stdint.h>

// Problem constants
#define BB 2
#define SS 2048
#define DD 1024
#define FF 4096
#define HH 16
#define DKK 64
#define MM (BB*SS)          // 4096

#define WQ0 0
#define WK0 (DD*DD)
#define WV0 (2*DD*DD)
#define WO0 (3*DD*DD)
#define W10 (4*DD*DD)
#define W20 (8*DD*DD)
#define WTOT (12*DD*DD)

// ---------------- scratch (static device memory; no allocation APIs) ----------------
__device__ __align__(256) float  g_q  [MM*DD];     // fp32 Q for flash (split in-kernel)
__device__ __align__(256) __half g_khh[MM*DD];
__device__ __align__(256) __half g_khl[MM*DD];
__device__ __align__(256) __half g_vh [MM*DD];
__device__ __align__(256) __half g_ath[MM*DD];     // attention output (fp16)
__device__ __align__(256) float  g_x1 [MM*DD];
__device__ __align__(256) __half g_xnh[MM*DD];
__device__ __align__(256) __half g_xnl[MM*DD];
__device__ __align__(256) __half g_hh [MM*FF];
__device__ __align__(256) __half g_wh [WTOT];
__device__ __align__(256) __half g_wl [WTOT];

// ---------------- helpers ----------------
__device__ __forceinline__ float warpSum(float v) {
#pragma unroll
    for (int o = 16; o > 0; o >>= 1) v += __shfl_xor_sync(0xffffffffu, v, o);
    return v;
}
__device__ float blockSum(float v) {
    __shared__ float sh[8];
    int lane = threadIdx.x & 31, w = threadIdx.x >> 5;
    v = warpSum(v);
    if (lane == 0) sh[w] = v;
    __syncthreads();
    if (w == 0) {
        float t = (lane < 8) ? sh[lane] : 0.0f;
        t = warpSum(t);
        if (lane == 0) sh[0] = t;
    }
    __syncthreads();
    float out = sh[0];
    __syncthreads();
    return out;
}
__device__ __forceinline__ void hsplit(float f, __half& h, __half& l) {
    h = __float2half_rn(f);
    l = __float2half_rn(f - __half2float(h));
}

// ---------------- fused weight-split kernel: all 6 weights in one launch ----------------
// 3M float4 total. 3072 blocks x 256 threads x 4 float4 (independent -> MLP=4).
// Region boundaries are block-aligned: attn weights = 256 blocks each, w1/w2 = 1024 each.
__global__ void conv_all(const float* __restrict__ wq, const float* __restrict__ wk,
                         const float* __restrict__ wv, const float* __restrict__ wo,
                         const float* __restrict__ w1, const float* __restrict__ w2,
                         __half* __restrict__ wh, __half* __restrict__ wl) {
    const int bid = blockIdx.x, t = threadIdx.x;
    const float* src;
    long long doff;        // element offset into wh/wl
    int lbase;             // float4 offset within region
    if (bid < 1024) {
        int r = bid >> 8;
        src = (r == 0) ? wq : (r == 1) ? wk : (r == 2) ? wv : wo;
        doff = (long long)r << 20;
        lbase = (bid & 255) * 1024;
    } else if (bid < 2048) {
        src = w1; doff = W10; lbase = (bid - 1024) * 1024;
    } else {
        src = w2; doff = W20; lbase = (bid - 2048) * 1024;
    }
    float4 v[4];
#pragma unroll
    for (int i = 0; i < 4; i++)
        v[i] = ((const float4*)src)[lbase + t + i * 256];
    __half2* ho = (__half2*)(wh + doff);
    __half2* lo = (__half2*)(wl + doff);
#pragma unroll
    for (int i = 0; i < 4; i++) {
        int fi = lbase + t + i * 256;
        __half h0, h1, h2, h3, l0, l1, l2, l3;
        hsplit(v[i].x, h0, l0); hsplit(v[i].y, h1, l1);
        hsplit(v[i].z, h2, l2); hsplit(v[i].w, h3, l3);
        __half2 p;
        p.x = h0; p.y = h1; ho[2 * fi] = p;
        p.x = h2; p.y = h3; ho[2 * fi + 1] = p;
        p.x = l0; p.y = l1; lo[2 * fi] = p;
        p.x = l2; p.y = l3; lo[2 * fi + 1] = p;
    }
}

// ---------------- LayerNorm -> hi/lo fp16 ----------------
__global__ void ln_kernel(const float* __restrict__ x,
                          __half* __restrict__ yh, __half* __restrict__ yl,
                          const float* __restrict__ alpha, const float* __restrict__ beta) {
    long long row = blockIdx.x;
    const float* xr = x + row * DD;
    float v[4];
    float s = 0.0f;
#pragma unroll
    for (int r = 0; r < 4; r++) {
        v[r] = xr[threadIdx.x + r * 256];
        s += v[r];
    }
    float mean = blockSum(s) * (1.0f / DD);
    float s2 = 0.0f;
#pragma unroll
    for (int r = 0; r < 4; r++) {
        float d = v[r] - mean;
        s2 += d * d;
    }
    float var = blockSum(s2) * (1.0f / (DD - 1));
    float a = alpha[0], b = beta[0];
    float inv = a / (sqrtf(var) + 1e-6f);
#pragma unroll
    for (int r = 0; r < 4; r++) {
        int idx = threadIdx.x + r * 256;
        float o = (v[r] - mean) * inv + b;
        __half h, l;
        hsplit(o, h, l);
        yh[row * DD + idx] = h;
        yl[row * DD + idx] = l;
    }
}

// ---------------- PTX primitives ----------------
__device__ __forceinline__ void mma_f16(float* c, const uint32_t* a,
                                        uint32_t b0, uint32_t b1) {
    asm volatile(
        "mma.sync.aligned.m16n8k16.row.col.f32.f16.f16.f32 "
        "{%0,%1,%2,%3},{%4,%5,%6,%7},{%8,%9},{%0,%1,%2,%3};"
        : "+f"(c[0]), "+f"(c[1]), "+f"(c[2]), "+f"(c[3])
        : "r"(a[0]), "r"(a[1]), "r"(a[2]), "r"(a[3]), "r"(b0), "r"(b1));
}
__device__ __forceinline__ void ldmx4(uint32_t addr, uint32_t& r0, uint32_t& r1,
                                      uint32_t& r2, uint32_t& r3) {
    asm volatile("ldmatrix.sync.aligned.m8n8.x4.shared.b16 {%0,%1,%2,%3}, [%4];"
                 : "=r"(r0), "=r"(r1), "=r"(r2), "=r"(r3) : "r"(addr));
}
__device__ __forceinline__ void ldmx2t(uint32_t addr, uint32_t& r0, uint32_t& r1) {
    asm volatile("ldmatrix.sync.aligned.m8n8.x2.trans.shared.b16 {%0,%1}, [%2];"
                 : "=r"(r0), "=r"(r1) : "r"(addr));
}
__device__ __forceinline__ void cp16(uint32_t d, const void* s) {
    asm volatile("cp.async.cg.shared.global [%0], [%1], 16;" :: "r"(d), "l"(s));
}
__device__ __forceinline__ void cpcommit() { asm volatile("cp.async.commit_group;"); }
template<int N> __device__ __forceinline__ void cpwait() {
    asm volatile("cp.async.wait_group %0;" :: "n"(N));
}
__device__ __forceinline__ uint32_t s2u(const void* p) {
    uint32_t a;
    asm("{ .reg .u64 t; cvta.to.shared.u64 t, %1; cvt.u32.u64 %0, t; }" : "=r"(a) : "l"(p));
    return a;
}
__device__ __forceinline__ uint32_t packh2(float a, float b) {
    __half2 h = __floats2half2_rn(a, b);
    return *(uint32_t*)&h;
}

// ---------------- fp16 NT GEMM ----------------
// C[m,n] = sum_k A[m,k]*B[n,k]. BM=BN=128, 2-stage cp.async, ldmatrix.
// SPLIT=1: 3-mma hi/lo split, BK=32 (80KB smem). SPLIT=0: plain 1-mma, BK=64
// (74KB smem, half the barriers per K). Both 2 CTAs/SM.
// outMode: 0 = fp32 C (+res opt), 1 = half Ch (hi only, relu opt), 2 = half Ch+Cl.
template<int SPLIT>
__global__ void __launch_bounds__(256, 2)
gemm_h(const __half* __restrict__ Ah, const __half* __restrict__ Al,
       const __half* __restrict__ Bh, const __half* __restrict__ Bl,
       const float* __restrict__ bias, const float* __restrict__ res,
       float* __restrict__ C, __half* __restrict__ Ch, __half* __restrict__ Cl,
       int M, int N, int K, int doRelu, int doRes, int outMode)
{
    constexpr int NARR = SPLIT ? 4 : 2;
    constexpr int BKD  = SPLIT ? 32 : 64;
    constexpr int STRD = BKD + 8;            // halves per smem row; conflict-free ldmatrix
    constexpr int TILE = 128 * STRD;         // halves per array per stage
    constexpr int CPR  = BKD / 8;            // 16B chunks per row
    constexpr int CPI  = BKD / 16;           // cp16 iterations per array per thread
    extern __shared__ __half sm[];
    const uint32_t sbase = s2u(sm);

    const int m0 = blockIdx.y * 128, n0 = blockIdx.x * 128;
    const int t = threadIdx.x, lane = t & 31, w = t >> 5;
    const int gid = lane >> 2, tig = lane & 3;
    const int wm = w >> 2, wn = w & 3;
    const int mBase = wm * 64, nBase = wn * 32;
    const int lr = lane & 7, lj = lane >> 3;

    float acc[4][4][4];
#pragma unroll
    for (int i = 0; i < 4; i++)
#pragma unroll
        for (int j = 0; j < 4; j++)
#pragma unroll
            for (int r = 0; r < 4; r++) acc[i][j][r] = 0.0f;

    const __half* gsrc[NARR];
    if (SPLIT) { gsrc[0] = Ah; gsrc[1] = Al; gsrc[2] = Bh; gsrc[3] = Bl; }
    else       { gsrc[0] = Ah; gsrc[1] = Bh; }

    auto issue = [&](int kt, int s) {
        int k0 = kt * BKD;
#pragma unroll
        for (int arr = 0; arr < NARR; arr++) {
            const int rb = (arr < (SPLIT ? 2 : 1)) ? m0 : n0;
            const __half* src = gsrc[arr];
            uint32_t dst = sbase + (uint32_t)(s * NARR + arr) * (TILE * 2);
#pragma unroll
            for (int i = 0; i < CPI; i++) {
                int c = t + i * 256;
                int row = c / CPR, col = (c % CPR) * 8;
                cp16(dst + (uint32_t)(row * STRD + col) * 2,
                     src + (long long)(rb + row) * K + k0 + col);
            }
        }
    };

    const int KT = K / BKD;
    issue(0, 0); cpcommit();

    for (int kt = 0; kt < KT; kt++) {
        cpwait<0>();
        __syncthreads();
        if (kt + 1 < KT) { issue(kt + 1, (kt + 1) & 1); cpcommit(); }

        const int buf = kt & 1;
        const uint32_t uAh = sbase + (uint32_t)(buf * NARR + 0) * (TILE * 2);
        const uint32_t uAl = SPLIT ? sbase + (uint32_t)(buf * NARR + 1) * (TILE * 2) : 0;
        const uint32_t uBh = sbase + (uint32_t)(buf * NARR + (SPLIT ? 2 : 1)) * (TILE * 2);
        const uint32_t uBl = SPLIT ? sbase + (uint32_t)(buf * NARR + 3) * (TILE * 2) : 0;

#pragma unroll
        for (int kk = 0; kk < BKD; kk += 16) {
            uint32_t bh[4][2], bl[4][2];
#pragma unroll
            for (int p = 0; p < 2; p++) {
                uint32_t off = (uint32_t)((nBase + p * 16 + lr + (lj >> 1) * 8) * STRD
                                          + kk + (lj & 1) * 8) * 2;
                ldmx4(uBh + off, bh[2 * p][0], bh[2 * p][1], bh[2 * p + 1][0], bh[2 * p + 1][1]);
                if (SPLIT)
                    ldmx4(uBl + off, bl[2 * p][0], bl[2 * p][1], bl[2 * p + 1][0], bl[2 * p + 1][1]);
            }
#pragma unroll
            for (int mt = 0; mt < 4; mt++) {
                uint32_t ah[4], al4[4];
                uint32_t aoff = (uint32_t)((mBase + mt * 16 + lr + (lj & 1) * 8) * STRD
                                           + kk + (lj >> 1) * 8) * 2;
                ldmx4(uAh + aoff, ah[0], ah[1], ah[2], ah[3]);
                if (SPLIT) ldmx4(uAl + aoff, al4[0], al4[1], al4[2], al4[3]);
#pragma unroll
                for (int nt = 0; nt < 4; nt++) {
                    mma_f16(acc[mt][nt], ah, bh[nt][0], bh[nt][1]);
                    if (SPLIT) {
                        mma_f16(acc[mt][nt], ah, bl[nt][0], bl[nt][1]);
                        mma_f16(acc[mt][nt], al4, bh[nt][0], bh[nt][1]);
                    }
                }
            }
        }
    }

    // ---- epilogue
#pragma unroll
    for (int mt = 0; mt < 4; mt++) {
#pragma unroll
        for (int nt = 0; nt < 4; nt++) {
            int row = m0 + mBase + mt * 16 + gid;
            int col = n0 + nBase + nt * 8 + tig * 2;
            float b0 = bias[col], b1 = bias[col + 1];
#pragma unroll
            for (int half = 0; half < 2; half++) {
                int r = row + half * 8;
                float v0 = acc[mt][nt][half * 2 + 0] + b0;
                float v1 = acc[mt][nt][half * 2 + 1] + b1;
                if (doRelu) { v0 = fmaxf(v0, 0.f); v1 = fmaxf(v1, 0.f); }
                if (outMode == 0) {
                    if (doRes) {
                        float2 rr = *(const float2*)(res + (long long)r * N + col);
                        v0 += rr.x; v1 += rr.y;
                    }
                    *(float2*)(C + (long long)r * N + col) = make_float2(v0, v1);
                } else if (outMode == 1) {
                    __half2 p = __floats2half2_rn(v0, v1);
                    *(__half2*)(Ch + (long long)r * N + col) = p;
                } else {
                    __half h0, l0, h1, l1;
                    hsplit(v0, h0, l0); hsplit(v1, h1, l1);
                    __half2 p;
                    p.x = h0; p.y = h1;
                    *(__half2*)(Ch + (long long)r * N + col) = p;
                    p.x = l0; p.y = l1;
                    *(__half2*)(Cl + (long long)r * N + col) = p;
                }
            }
        }
    }
}

#define GEMM_SMEM_S1 (2 * 4 * 128 * 40 * 2)   // 81920
#define GEMM_SMEM_S0 (2 * 2 * 128 * 72 * 2)   // 73728

// ---------------- flash attention, fp16, 3-stage K/V pipeline ----------------
#define KST 72                      // halves per smem row (144B)
#define FL_BUF (128*KST)            // halves per array per stage
#define QSTR 68
#define NKB (SS/128)                // 16
#define FLASH_SMEM (9 * FL_BUF * 2) // 3 stages x 3 arrays

__global__ void __launch_bounds__(256, 1)
flash_kernel(const float* __restrict__ Q, const __half* __restrict__ Khh,
             const __half* __restrict__ Khl, const __half* __restrict__ Vh,
             const int* __restrict__ mask, __half* __restrict__ O)
{
    extern __shared__ __half fsm[];
    __shared__ int Ms[2][128];
    const uint32_t sb = s2u(fsm);

    const int bh = blockIdx.y;
    const int b = bh >> 4, h = bh & 15;
    const int q0 = blockIdx.x * 128;
    const int t = threadIdx.x, lane = t & 31, w = t >> 5;
    const int gid = lane >> 2, tig = lane & 3;

    auto issue = [&](int kb, int buf) {
        const long long rowbase = (long long)b * SS + kb * 128;
        const __half* srcs[3] = { Khh, Khl, Vh };
#pragma unroll
        for (int arr = 0; arr < 3; arr++) {
            const __half* src = srcs[arr];
            uint32_t dst = sb + (uint32_t)(buf * 3 + arr) * (FL_BUF * 2);
#pragma unroll
            for (int i = 0; i < 4; i++) {
                int idx = t + i * 256;
                int row = idx >> 3, pc = idx & 7;
                cp16(dst + (uint32_t)(row * KST + pc * 8) * 2,
                     src + (rowbase + row) * DD + h * DKK + pc * 8);
            }
        }
    };

    issue(0, 0); cpcommit();
    issue(1, 1); cpcommit();

    float* Qs = (float*)(fsm + 6 * FL_BUF);     // overlay on buffer 2 (untouched yet)
    {
        const float* Qbase = Q + ((long long)(b * SS + q0)) * DD + h * DKK;
        for (int i = t; i < 2048; i += 256) {
            int r = i >> 4, c = (i & 15) * 4;
            *(float4*)&Qs[r * QSTR + c] = *(const float4*)(Qbase + (long long)r * DD + c);
        }
    }
    __syncthreads();

    uint32_t qh[4][4], ql[4][4];
    {
        int r0 = w * 16 + gid;
#pragma unroll
        for (int ks = 0; ks < 4; ks++) {
            int k0 = ks * 16;
            float f00 = Qs[r0 * QSTR + k0 + 2 * tig],       f01 = Qs[r0 * QSTR + k0 + 2 * tig + 1];
            float f10 = Qs[(r0 + 8) * QSTR + k0 + 2 * tig], f11 = Qs[(r0 + 8) * QSTR + k0 + 2 * tig + 1];
            float f20 = Qs[r0 * QSTR + k0 + 8 + 2 * tig],       f21 = Qs[r0 * QSTR + k0 + 8 + 2 * tig + 1];
            float f30 = Qs[(r0 + 8) * QSTR + k0 + 8 + 2 * tig], f31 = Qs[(r0 + 8) * QSTR + k0 + 8 + 2 * tig + 1];
            __half h0, l0, h1, l1;
            hsplit(f00, h0, l0); hsplit(f01, h1, l1);
            qh[ks][0] = packh2(__half2float(h0), __half2float(h1));
            ql[ks][0] = packh2(__half2float(l0), __half2float(l1));
            hsplit(f10, h0, l0); hsplit(f11, h1, l1);
            qh[ks][1] = packh2(__half2float(h0), __half2float(h1));
            ql[ks][1] = packh2(__half2float(l0), __half2float(l1));
            hsplit(f20, h0, l0); hsplit(f21, h1, l1);
            qh[ks][2] = packh2(__half2float(h0), __half2float(h1));
            ql[ks][2] = packh2(__half2float(l0), __half2float(l1));
            hsplit(f30, h0, l0); hsplit(f31, h1, l1);
            qh[ks][3] = packh2(__half2float(h0), __half2float(h1));
            ql[ks][3] = packh2(__half2float(l0), __half2float(l1));
        }
    }

    float acc[8][4];
#pragma unroll
    for (int i = 0; i < 8; i++)
#pragma unroll
        for (int r = 0; r < 4; r++) acc[i][r] = 0.0f;
    float mrow0 = -1e30f, mrow1 = -1e30f;
    float lrow0 = 0.0f, lrow1 = 0.0f;

    for (int kb = 0; kb < NKB; kb++) {
        if (kb + 1 < NKB) cpwait<1>(); else cpwait<0>();
        if (t < 128) Ms[kb & 1][t] = mask[(long long)b * SS + kb * 128 + t];
        __syncthreads();            // buffer kb%3 ready; Q-frag reads done (kb==0)
        if (kb + 2 < NKB) { issue(kb + 2, (kb + 2) % 3); cpcommit(); }

        const int buf = kb % 3;
        const uint32_t bKhh = sb + (uint32_t)(buf * 3 + 0) * (FL_BUF * 2);
        const uint32_t bKhl = sb + (uint32_t)(buf * 3 + 1) * (FL_BUF * 2);
        const uint32_t bV   = sb + (uint32_t)(buf * 3 + 2) * (FL_BUF * 2);
        const int lr = lane & 7, lj = lane >> 3;
        const int* Mrow = Ms[kb & 1];

        float s[16][4];
#pragma unroll
        for (int nt = 0; nt < 16; nt++) {
            s[nt][0] = 0.f; s[nt][1] = 0.f; s[nt][2] = 0.f; s[nt][3] = 0.f;
        }
#pragma unroll
        for (int ks = 0; ks < 4; ks++) {
#pragma unroll
            for (int pp = 0; pp < 8; pp++) {
                uint32_t off = (uint32_t)((pp * 16 + lr + (lj >> 1) * 8) * KST
                                          + ks * 16 + (lj & 1) * 8) * 2;
                uint32_t r0, r1, r2, r3, e0, e1, e2, e3;
                ldmx4(bKhh + off, r0, r1, r2, r3);
                ldmx4(bKhl + off, e0, e1, e2, e3);
                mma_f16(s[2 * pp],     qh[ks], r0, r1);
                mma_f16(s[2 * pp],     ql[ks], r0, r1);
                mma_f16(s[2 * pp],     qh[ks], e0, e1);
                mma_f16(s[2 * pp + 1], qh[ks], r2, r3);
                mma_f16(s[2 * pp + 1], ql[ks], r2, r3);
                mma_f16(s[2 * pp + 1], qh[ks], e2, e3);
            }
        }

#pragma unroll
        for (int nt = 0; nt < 16; nt++) {
            int c = nt * 8 + 2 * tig;
            if (Mrow[c] == 0)     { s[nt][0] = -1e30f; s[nt][2] = -1e30f; }
            if (Mrow[c + 1] == 0) { s[nt][1] = -1e30f; s[nt][3] = -1e30f; }
        }

        float tm0 = -1e30f, tm1 = -1e30f;
#pragma unroll
        for (int nt = 0; nt < 16; nt++) {
            tm0 = fmaxf(tm0, fmaxf(s[nt][0], s[nt][1]));
            tm1 = fmaxf(tm1, fmaxf(s[nt][2], s[nt][3]));
        }
        tm0 = fmaxf(tm0, __shfl_xor_sync(0xffffffffu, tm0, 1));
        tm0 = fmaxf(tm0, __shfl_xor_sync(0xffffffffu, tm0, 2));
        tm1 = fmaxf(tm1, __shfl_xor_sync(0xffffffffu, tm1, 1));
        tm1 = fmaxf(tm1, __shfl_xor_sync(0xffffffffu, tm1, 2));
        float mn0 = fmaxf(mrow0, tm0), mn1 = fmaxf(mrow1, tm1);
        float sc0 = __expf(mrow0 - mn0), sc1 = __expf(mrow1 - mn1);
        mrow0 = mn0; mrow1 = mn1;
        float rs0 = 0.f, rs1 = 0.f;
#pragma unroll
        for (int nt = 0; nt < 16; nt++) {
            s[nt][0] = __expf(s[nt][0] - mn0);
            s[nt][1] = __expf(s[nt][1] - mn0);
            s[nt][2] = __expf(s[nt][2] - mn1);
            s[nt][3] = __expf(s[nt][3] - mn1);
            rs0 += s[nt][0] + s[nt][1];
            rs1 += s[nt][2] + s[nt][3];
        }
        rs0 += __shfl_xor_sync(0xffffffffu, rs0, 1);
        rs0 += __shfl_xor_sync(0xffffffffu, rs0, 2);
        rs1 += __shfl_xor_sync(0xffffffffu, rs1, 1);
        rs1 += __shfl_xor_sync(0xffffffffu, rs1, 2);
        lrow0 = lrow0 * sc0 + rs0;
        lrow1 = lrow1 * sc1 + rs1;
#pragma unroll
        for (int nt = 0; nt < 8; nt++) {
            acc[nt][0] *= sc0; acc[nt][1] *= sc0;
            acc[nt][2] *= sc1; acc[nt][3] *= sc1;
        }

        const int li = lane & 15;
#pragma unroll
        for (int ks = 0; ks < 8; ks++) {
            uint32_t a[4];
            a[0] = packh2(s[2 * ks][0],     s[2 * ks][1]);
            a[1] = packh2(s[2 * ks][2],     s[2 * ks][3]);
            a[2] = packh2(s[2 * ks + 1][0], s[2 * ks + 1][1]);
            a[3] = packh2(s[2 * ks + 1][2], s[2 * ks + 1][3]);
#pragma unroll
            for (int nt2 = 0; nt2 < 8; nt2++) {
                uint32_t off = (uint32_t)((ks * 16 + (li & 7) + (li >> 3) * 8) * KST
                                          + nt2 * 8) * 2;
                uint32_t b0, b1;
                ldmx2t(bV + off, b0, b1);
                mma_f16(acc[nt2], a, b0, b1);
            }
        }
    }

    float inv0 = 1.0f / lrow0, inv1 = 1.0f / lrow1;
    long long rowg = (long long)(b * SS + q0 + w * 16 + gid);
#pragma unroll
    for (int nt = 0; nt < 8; nt++) {
        int col = h * DKK + nt * 8 + 2 * tig;
        __half2 p0 = __floats2half2_rn(acc[nt][0] * inv0, acc[nt][1] * inv0);
        __half2 p1 = __floats2half2_rn(acc[nt][2] * inv1, acc[nt][3] * inv1);
        *(__half2*)(O + rowg * DD + col) = p0;
        *(__half2*)(O + (rowg + 8) * DD + col) = p1;
    }
}

// ---------------- host launch ----------------
extern "C" void kernel_launch(void* const* d_in, const int* in_sizes, int n_in,
                              void* d_out, int out_size) {
    const float* x      = (const float*)d_in[0];
    const int*   mask   = (const int*)  d_in[1];
    const float* wq     = (const float*)d_in[2];
    const float* bq     = (const float*)d_in[3];
    const float* wk     = (const float*)d_in[4];
    const float* bk     = (const float*)d_in[5];
    const float* wv     = (const float*)d_in[6];
    const float* bv     = (const float*)d_in[7];
    const float* wo     = (const float*)d_in[8];
    const float* bo     = (const float*)d_in[9];
    const float* w1     = (const float*)d_in[10];
    const float* b1     = (const float*)d_in[11];
    const float* w2     = (const float*)d_in[12];
    const float* b2     = (const float*)d_in[13];
    const float* alpha1 = (const float*)d_in[14];
    const float* beta1  = (const float*)d_in[15];
    const float* alpha2 = (const float*)d_in[16];
    const float* beta2  = (const float*)d_in[17];
    float* out = (float*)d_out;

    float *q, *x1;
    __half *khh, *khl, *vh, *ath, *xnh, *xnl, *hh, *wh, *wl;
    cudaGetSymbolAddress((void**)&q,   g_q);
    cudaGetSymbolAddress((void**)&x1,  g_x1);
    cudaGetSymbolAddress((void**)&khh, g_khh);
    cudaGetSymbolAddress((void**)&khl, g_khl);
    cudaGetSymbolAddress((void**)&vh,  g_vh);
    cudaGetSymbolAddress((void**)&ath, g_ath);
    cudaGetSymbolAddress((void**)&xnh, g_xnh);
    cudaGetSymbolAddress((void**)&xnl, g_xnl);
    cudaGetSymbolAddress((void**)&hh,  g_hh);
    cudaGetSymbolAddress((void**)&wh,  g_wh);
    cudaGetSymbolAddress((void**)&wl,  g_wl);

    cudaFuncSetAttribute(flash_kernel, cudaFuncAttributeMaxDynamicSharedMemorySize, FLASH_SMEM);
    cudaFuncSetAttribute(gemm_h<1>, cudaFuncAttributeMaxDynamicSharedMemorySize, GEMM_SMEM_S1);
    cudaFuncSetAttribute(gemm_h<0>, cudaFuncAttributeMaxDynamicSharedMemorySize, GEMM_SMEM_S0);

    // launch 1: all weight splits fused (MLP-optimized)
    conv_all<<<3072, 256>>>(wq, wk, wv, wo, w1, w2, wh, wl);

    // launch 2: LN1 -> xn hi/lo
    ln_kernel<<<MM, 256>>>(x, xnh, xnl, alpha1, beta1);

    // launches 3-5: projections
    {
        dim3 g(DD / 128, MM / 128);
        gemm_h<1><<<g, 256, GEMM_SMEM_S1>>>(xnh, xnl, wh + WQ0, wl + WQ0, bq, nullptr,
                                            q, nullptr, nullptr, MM, DD, DD, 0, 0, 0);
        gemm_h<1><<<g, 256, GEMM_SMEM_S1>>>(xnh, xnl, wh + WK0, wl + WK0, bk, nullptr,
                                            nullptr, khh, khl, MM, DD, DD, 0, 0, 2);
        gemm_h<0><<<g, 256, GEMM_SMEM_S0>>>(xnh, nullptr, wh + WV0, nullptr, bv, nullptr,
                                            nullptr, vh, nullptr, MM, DD, DD, 0, 0, 1);
    }

    // launch 6: fused attention (ncu -s 5 -c 1 should capture this)
    {
        dim3 g(SS / 128, BB * HH);
        flash_kernel<<<g, 256, FLASH_SMEM>>>(q, khh, khl, vh, mask, ath);
    }

    // x1 = x + attn @ wo^T + bo  (plain fp16)
    {
        dim3 g(DD / 128, MM / 128);
        gemm_h<0><<<g, 256, GEMM_SMEM_S0>>>(ath, nullptr, wh + WO0, nullptr, bo, x,
                                            x1, nullptr, nullptr, MM, DD, DD, 0, 1, 0);
    }

    // LN2 -> xn hi/lo
    ln_kernel<<<MM, 256>>>(x1, xnh, xnl, alpha2, beta2);

    // h = relu(xn @ w1^T + b1) -> fp16 (plain)
    {
        dim3 g(FF / 128, MM / 128);
        gemm_h<0><<<g, 256, GEMM_SMEM_S0>>>(xnh, nullptr, wh + W10, nullptr, b1, nullptr,
                                            nullptr, hh, nullptr, MM, FF, DD, 1, 0, 1);
    }

    // out = x1 + h @ w2^T + b2  (plain fp16)
    {
        dim3 g(DD / 128, MM / 128);
        gemm_h<0><<<g, 256, GEMM_SMEM_S0>>>(hh, nullptr, wh + W20, nullptr, b2, x1,
                                            out, nullptr, nullptr, MM, DD, FF, 0, 1, 0);
    }
}